// round 1
// baseline (speedup 1.0000x reference)
#include <cuda_runtime.h>
#include <cstdint>

typedef unsigned long long ull_t;

// packed f32x2 fused multiply-add (Blackwell): acc.lo += a.lo*b.lo; acc.hi += a.hi*b.hi
__device__ __forceinline__ void ffma2(ull_t &acc, ull_t a, ull_t b) {
    asm volatile("fma.rn.f32x2 %0, %1, %2, %0;" : "+l"(acc) : "l"(a), "l"(b));
}

__device__ __forceinline__ float hsum2(ull_t v) {
    float lo, hi;
    asm("mov.b64 {%0,%1}, %2;" : "=f"(lo), "=f"(hi) : "l"(v));
    return lo + hi;
}

__device__ __forceinline__ void cp_async16(uint32_t dst, const void* src, int src_sz) {
    asm volatile("cp.async.cg.shared.global [%0], [%1], 16, %2;"
                 :: "r"(dst), "l"(src), "r"(src_sz));
}
__device__ __forceinline__ void cp_commit() {
    asm volatile("cp.async.commit_group;");
}
__device__ __forceinline__ void cp_wait1() {
    asm volatile("cp.async.wait_group 1;" ::: "memory");
}

// Specialized for H=64, D=32 (fixed by the problem). Runtime B, T.
// Block = 128 threads = 2 batch elements (one warp per SMSP slice per batch-half).
// Thread (sb, j) owns output channel j of batch blockIdx.x*2+sb.
__global__ void __launch_bounds__(128, 1)
ctrnn_scan_kernel(const float* __restrict__ x,
                  const float* __restrict__ W_in,
                  const float* __restrict__ b_in,
                  const float* __restrict__ W_hh,
                  const float* __restrict__ b_hh,
                  float* __restrict__ out,
                  int B, int T)
{
    constexpr int H  = 64;
    constexpr int D  = 32;
    constexpr int CH = 32;   // timesteps per x-staging chunk

    const int tid = threadIdx.x;
    const int sb  = tid >> 6;        // which of the 2 batches in this block
    const int j   = tid & 63;        // output channel
    const int b   = blockIdx.x * 2 + sb;
    const bool active = (b < B);
    const int bc  = active ? b : (B - 1);   // clamped for safe addressing

    // h double buffer + x staging double buffer
    __shared__ __align__(16) float hbuf[2][2][H];          // [ping-pong][sb][H]
    __shared__ __align__(16) float xbuf[2][2][CH * D];     // [ping-pong][sb][CH*D]

    // ---- weights into registers as packed f32x2 pairs (k, k+1 contiguous) ----
    ull_t wu[H / 2];
    {
        const ulonglong2* wr = reinterpret_cast<const ulonglong2*>(W_hh + j * H);
#pragma unroll
        for (int m = 0; m < H / 4; m++) {
            ulonglong2 v = wr[m];
            wu[2 * m]     = v.x;
            wu[2 * m + 1] = v.y;
        }
    }
    ull_t iu[D / 2];
    {
        const ulonglong2* wr = reinterpret_cast<const ulonglong2*>(W_in + j * D);
#pragma unroll
        for (int m = 0; m < D / 4; m++) {
            ulonglong2 v = wr[m];
            iu[2 * m]     = v.x;
            iu[2 * m + 1] = v.y;
        }
    }
    const float bias  = b_hh[j] + b_in[j];               // pre = x@Win + b_in + h@Whh + b_hh
    const float alpha = (float)(16.67 / 40.0);
    const float oma   = (float)(1.0 - 16.67 / 40.0);

    hbuf[0][sb][j] = 0.0f;   // h0 = 0
    float hj = 0.0f;         // this thread's own h_j (leak term)

    const int nchunk = (T + CH - 1) / CH;

    // ---- async x chunk loader: 64 threads per batch copy CH*D*4 = 4KB contiguous ----
    auto issue_chunk = [&](int c, int buf) {
        const size_t base_elem = ((size_t)bc * T + (size_t)c * CH) * D;
        const char* srcb = (const char*)(x + base_elem);
        uint32_t dstb = (uint32_t)__cvta_generic_to_shared(&xbuf[buf][sb][0]);
#pragma unroll
        for (int r = 0; r < (CH * D * 4) / (64 * 16); r++) {
            int off16 = j + 64 * r;                 // 16B-unit index within chunk
            int row   = off16 / (D / 4);            // timestep row of this 16B piece
            bool ok   = active && (c * CH + row) < T;
            const void* src = ok ? (const void*)(srcb + (size_t)off16 * 16)
                                 : (const void*)x;  // safe dummy addr, zero-filled
            cp_async16(dstb + off16 * 16, src, ok ? 16 : 0);
        }
        cp_commit();
    };

    // prologue: stage chunks 0 and 1
    issue_chunk(0, 0);
    if (nchunk > 1) issue_chunk(1, 1); else cp_commit();

    int cur = 0;
    const size_t outbase = (size_t)bc * T * H + j;

    for (int c = 0; c < nchunk; c++) {
        cp_wait1();            // chunk c landed (chunk c+1 may still be in flight)
        __syncthreads();       // all threads see chunk c + hbuf init / prior writes

        const int xb   = c & 1;
        const int tend = min(CH, T - c * CH);
        const size_t obase_c = outbase + (size_t)c * CH * H;

        if (tend == CH) {
#pragma unroll 4
            for (int tt = 0; tt < CH; tt++) {
                const ulonglong2* hp = reinterpret_cast<const ulonglong2*>(hbuf[cur][sb]);
                const ulonglong2* xp = reinterpret_cast<const ulonglong2*>(&xbuf[xb][sb][tt * D]);
                ull_t a0 = 0ull, a1 = 0ull, a2 = 0ull, a3 = 0ull;
#pragma unroll
                for (int m = 0; m < 16; m++) {
                    ulonglong2 hv = hp[m];
                    ffma2((m & 1) ? a1 : a0, wu[2 * m],     hv.x);
                    ffma2((m & 1) ? a3 : a2, wu[2 * m + 1], hv.y);
                }
#pragma unroll
                for (int m = 0; m < 8; m++) {
                    ulonglong2 xv = xp[m];
                    ffma2((m & 1) ? a1 : a0, iu[2 * m],     xv.x);
                    ffma2((m & 1) ? a3 : a2, iu[2 * m + 1], xv.y);
                }
                float s = (hsum2(a0) + hsum2(a1)) + (hsum2(a2) + hsum2(a3)) + bias;
                float hnew = fmaxf(fmaf(s, alpha, hj * oma), 0.0f);
                hbuf[cur ^ 1][sb][j] = hnew;
                if (active) out[obase_c + (size_t)tt * H] = hnew;
                hj = hnew;
                cur ^= 1;
                __syncthreads();
            }
        } else {
            for (int tt = 0; tt < tend; tt++) {
                const ulonglong2* hp = reinterpret_cast<const ulonglong2*>(hbuf[cur][sb]);
                const ulonglong2* xp = reinterpret_cast<const ulonglong2*>(&xbuf[xb][sb][tt * D]);
                ull_t a0 = 0ull, a1 = 0ull, a2 = 0ull, a3 = 0ull;
#pragma unroll
                for (int m = 0; m < 16; m++) {
                    ulonglong2 hv = hp[m];
                    ffma2((m & 1) ? a1 : a0, wu[2 * m],     hv.x);
                    ffma2((m & 1) ? a3 : a2, wu[2 * m + 1], hv.y);
                }
#pragma unroll
                for (int m = 0; m < 8; m++) {
                    ulonglong2 xv = xp[m];
                    ffma2((m & 1) ? a1 : a0, iu[2 * m],     xv.x);
                    ffma2((m & 1) ? a3 : a2, iu[2 * m + 1], xv.y);
                }
                float s = (hsum2(a0) + hsum2(a1)) + (hsum2(a2) + hsum2(a3)) + bias;
                float hnew = fmaxf(fmaf(s, alpha, hj * oma), 0.0f);
                hbuf[cur ^ 1][sb][j] = hnew;
                if (active) out[obase_c + (size_t)tt * H] = hnew;
                hj = hnew;
                cur ^= 1;
                __syncthreads();
            }
        }

        // stage chunk c+2 into the buffer chunk c just vacated
        if (c + 2 < nchunk) issue_chunk(c + 2, xb); else cp_commit();
    }

    // h_last appended after outputs
    if (active) out[(size_t)B * T * H + (size_t)b * H + j] = hj;
}

extern "C" void kernel_launch(void* const* d_in, const int* in_sizes, int n_in,
                              void* d_out, int out_size)
{
    const float* x    = (const float*)d_in[0];
    // d_in[1] = seq_lengths: forward-dead (mask only gates gradients)
    const float* W_in = (const float*)d_in[2];
    const float* b_in = (const float*)d_in[3];
    const float* W_hh = (const float*)d_in[4];
    const float* b_hh = (const float*)d_in[5];
    float* out = (float*)d_out;

    const int B = in_sizes[1];              // seq_lengths has B elements
    const int H = in_sizes[5];              // b_hh has H elements (== 64)
    const int D = in_sizes[2] / H;          // W_in is H*D        (== 32)
    const long long T = (long long)in_sizes[0] / ((long long)B * D);

    const int grid = (B + 1) / 2;
    ctrnn_scan_kernel<<<grid, 128>>>(x, W_in, b_in, W_hh, b_hh, out, B, (int)T);
}